// round 12
// baseline (speedup 1.0000x reference)
#include <cuda_runtime.h>
#include <math.h>
#include <stdint.h>

// Problem constants
#define TB   8192   // T
#define NB   128    // batch
#define NS   512    // states
#define NM   64     // symbols
#define NCL  16     // clusters (batch groups)
#define RPC  8      // batch rows per cluster
#define CPC  8      // CTAs per cluster (state slices)
#define NC   64     // state columns per CTA
#define PSD  76     // part s-dim pad (conflict-free ST + LD)
#define BLKW 264    // words per source block: 256 data [sp][b] + 8 lmax
#define BLKB 1056   // bytes per source block
#define TXB  8448   // expected tx bytes/step: 8 src blocks * 1056

// Dynamic SMEM layout (bytes)
#define SM_P     0                      // u32 p   [2][CPC][BLKW]   16896
#define SM_STG   16896                  // u32 stg [2][BLKW]         2112
#define SM_PART  19008                  // f32 part[2][2][RPC][PSD] 19456
#define SM_B     38464                  // f32 B_sh[NM][NC]         16384
#define SM_WMAX  54848                  // f32 wmax[8][8]             256
#define SM_C     55104                  // f64 c_sh[RPC]               64
#define SM_SYM   55168                  // u16 sym [RPC]               16
#define SM_MBAR  55184                  // u64 mbar[2]                 16
#define SM_TOTAL 55296

// Static device scratch
__device__ unsigned short g_sym[NB * TB];            // 2 MB: symbol per (b,t)

// ---- helpers ---------------------------------------------------------------
__device__ __forceinline__ uint32_t bf16x2(float hi, float lo) {
    uint32_t d;
    asm("cvt.rn.bf16x2.f32 %0, %1, %2;" : "=r"(d) : "f"(hi), "f"(lo));
    return d;
}
__device__ __forceinline__ void mma16816(float* d, const uint32_t* a,
                                         uint32_t b0, uint32_t b1) {
    asm("mma.sync.aligned.m16n8k16.row.col.f32.bf16.bf16.f32 "
        "{%0,%1,%2,%3}, {%4,%5,%6,%7}, {%8,%9}, {%0,%1,%2,%3};"
        : "+f"(d[0]), "+f"(d[1]), "+f"(d[2]), "+f"(d[3])
        : "r"(a[0]), "r"(a[1]), "r"(a[2]), "r"(a[3]), "r"(b0), "r"(b1));
}
__device__ __forceinline__ uint32_t mapa_sh(uint32_t addr, uint32_t rank) {
    uint32_t d;
    asm("mapa.shared::cluster.u32 %0, %1, %2;" : "=r"(d) : "r"(addr), "r"(rank));
    return d;
}
__device__ __forceinline__ uint32_t smem_u32(const void* p) {
    uint32_t a;
    asm("{ .reg .u64 t; cvta.to.shared.u64 t, %1; cvt.u32.u64 %0, t; }"
        : "=r"(a) : "l"(p));
    return a;
}
__device__ __forceinline__ void mbar_init(uint32_t addr, uint32_t count) {
    asm volatile("mbarrier.init.shared.b64 [%0], %1;" :: "r"(addr), "r"(count)
                 : "memory");
}
__device__ __forceinline__ void mbar_arm(uint32_t addr, uint32_t tx) {
    asm volatile("mbarrier.arrive.expect_tx.shared.b64 _, [%0], %1;"
                 :: "r"(addr), "r"(tx) : "memory");
}
__device__ __forceinline__ void mbar_wait(uint32_t addr, int parity) {
    asm volatile(
        "{\n\t.reg .pred P;\n"
        "W%=:\n\t"
        "mbarrier.try_wait.parity.acquire.cluster.shared::cta.b64 P, [%0], %1, 0x989680;\n\t"
        "@P bra D%=;\n\t"
        "bra W%=;\n"
        "D%=:\n\t}"
        :: "r"(addr), "r"(parity) : "memory");
}
// bulk SMEM -> remote-cluster-SMEM copy with tx completion on remote mbarrier
__device__ __forceinline__ void blkcp_s2s(uint32_t dst, uint32_t src,
                                          uint32_t bytes, uint32_t rmbar) {
    asm volatile("cp.async.bulk.shared::cluster.shared::cta"
                 ".mbarrier::complete_tx::bytes [%0], [%1], %2, [%3];"
                 :: "r"(dst), "r"(src), "r"(bytes), "r"(rmbar) : "memory");
}

// ---------------------------------------------------------------------------
// Kernel 0: collapse one-hot x[b,t,:] -> symbol index. 4 threads per position.
// ---------------------------------------------------------------------------
__global__ void extract_sym_kernel(const float* __restrict__ x) {
    int g = blockIdx.x * blockDim.x + threadIdx.x;
    int pos  = g >> 2;
    int part = g & 3;
    const float4* xp = reinterpret_cast<const float4*>(x) + (size_t)pos * 16 + part * 4;
    int found = 0;
#pragma unroll
    for (int i = 0; i < 4; i++) {
        float4 v = xp[i];
        int base = part * 16 + i * 4;
        if (v.x > 0.5f) found = base;
        if (v.y > 0.5f) found = base + 1;
        if (v.z > 0.5f) found = base + 2;
        if (v.w > 0.5f) found = base + 3;
    }
    found = max(found, __shfl_xor_sync(0xFFFFFFFFu, found, 1));
    found = max(found, __shfl_xor_sync(0xFFFFFFFFu, found, 2));
    if (part == 0) g_sym[pos] = (unsigned short)found;
}

// ---------------------------------------------------------------------------
// Kernel 1: persistent clustered forward recurrence, bf16 HMMA + fp32 accum,
//   bulk-copy DSMEM all-gather with mbarrier tx sync (no cluster barrier).
//   grid = 128 CTAs, cluster (8,1,1), 256 threads, dyn SMEM 55296 B.
//   p layout: [buf][src_rank][sp(32)][b(8)] words (+8 lmax words per block).
//   MMA:      warp w -> (mt = w&3 m16-tile, kh = w>>2 K-half), 16 HMMA.
//   Epilogue: thread -> (b = lane&7, sp = warp*4 + lane>>3); stage + bulk push.
// ---------------------------------------------------------------------------
__global__ void __cluster_dims__(CPC, 1, 1) __launch_bounds__(256, 1)
hmm_fwd_kernel(const float* __restrict__ A, const float* __restrict__ Bm,
               float* __restrict__ out)
{
    extern __shared__ __align__(16) char smem_raw[];
    uint32_t* p_w   = reinterpret_cast<uint32_t*>(smem_raw + SM_P);     // [2][CPC][BLKW]
    uint32_t* stg   = reinterpret_cast<uint32_t*>(smem_raw + SM_STG);   // [2][BLKW]
    float (*part)[2][RPC][PSD] =
        reinterpret_cast<float(*)[2][RPC][PSD]>(smem_raw + SM_PART);    // [buf][kh][n][m]
    float (*B_sh)[NC] = reinterpret_cast<float(*)[NC]>(smem_raw + SM_B);
    float (*wmax)[8]  = reinterpret_cast<float(*)[8]>(smem_raw + SM_WMAX);
    double*   c_sh    = reinterpret_cast<double*>(smem_raw + SM_C);
    unsigned short* sym_sh = reinterpret_cast<unsigned short*>(smem_raw + SM_SYM);

    const int tid  = threadIdx.x;
    const int lane = tid & 31;
    const int warp = tid >> 5;
    const int gid  = lane >> 2;   // mma group id
    const int tig  = lane & 3;    // thread in group
    const int mt   = warp & 3;    // m16 tile
    const int kh   = warp >> 2;   // K-half
    const int eb   = lane & 7;    // epilogue batch row
    const int esp  = warp * 4 + (lane >> 3);   // epilogue state pair (0..31)

    uint32_t r_;
    asm("mov.u32 %0, %%cluster_ctarank;" : "=r"(r_));
    const int r    = (int)r_;
    const int cl   = (int)blockIdx.x / CPC;
    const int col0 = r * NC;

    const uint32_t p_base    = smem_u32(p_w);
    const uint32_t stg_base  = smem_u32(stg);
    const uint32_t mbar_loc  = smem_u32(smem_raw + SM_MBAR);
    uint32_t p_rem[CPC], mbar_rem[CPC];
#pragma unroll
    for (int rr = 0; rr < CPC; rr++) {
        p_rem[rr]    = mapa_sh(p_base, rr);
        mbar_rem[rr] = mapa_sh(mbar_loc, rr);
    }

    if (tid == 0) { mbar_init(mbar_loc, 1); mbar_init(mbar_loc + 8, 1); }

    // ---- A fragments (constant): areg[16 kc][4], this warp's (mt, kh) ----
    uint32_t areg[16][4];
#pragma unroll
    for (int kc = 0; kc < 16; kc++) {
        int m0 = col0 + mt * 16 + gid;
        int k0 = kh * 256 + kc * 16 + tig * 2;
        const float* A0 = A + (size_t)k0 * NS;
        areg[kc][0] = bf16x2(A0[NS + m0],          A0[m0]);
        areg[kc][1] = bf16x2(A0[NS + m0 + 8],      A0[m0 + 8]);
        areg[kc][2] = bf16x2(A0[9 * NS + m0],      A0[8 * NS + m0]);
        areg[kc][3] = bf16x2(A0[9 * NS + m0 + 8],  A0[8 * NS + m0 + 8]);
    }

    // ---- emission slice (fp32) ----
    for (int i = tid; i < NM * NC; i += 256)
        B_sh[i >> 6][i & 63] = Bm[(size_t)(i >> 6) * NS + col0 + (i & 63)];

    if (tid < RPC) c_sh[tid] = 0.0;

    // ---- init buffer 0: only state 0 nonzero; lmax slots = true max ----
    for (int i = tid; i < CPC * BLKW; i += 256) {
        int rr = i / BLKW, w = i % BLKW;
        uint32_t v = 0;
        if (w >= 256) {                              // lmax word, b = w-256
            int b = w - 256;
            int s0 = g_sym[(size_t)(cl * RPC + b) * TB];
            v = __float_as_uint(Bm[(size_t)s0 * NS]);
        } else if (rr == 0 && (w >> 3) == 0) {       // sp==0 words
            int b = w & 7;
            int s0 = g_sym[(size_t)(cl * RPC + b) * TB];
            v = bf16x2(0.0f, Bm[(size_t)s0 * NS]);   // lo = state 0
        }
        p_w[i] = v;                                  // buffer 0
    }
    __syncthreads();
    asm volatile("barrier.cluster.arrive.aligned;" ::: "memory");
    asm volatile("barrier.cluster.wait.aligned;"   ::: "memory");

    int buf = 0, ph0 = 0, ph1 = 0;
    for (int t = 1; t < TB; t++) {
        const int bufn = buf ^ 1;
        // symbol prefetch (warp 0) — LDG issued before the wait
        unsigned short symr = 0;
        if (warp == 0 && lane < RPC)
            symr = __ldg(&g_sym[(size_t)(cl * RPC + lane) * TB + t]);

        // arm receiver mbarrier for incoming bufn data
        if (tid == 0) mbar_arm(mbar_loc + (bufn << 3), TXB);

        // wait for all of last step's data (buffer buf)
        if (t > 1) {
            if (buf == 0) { mbar_wait(mbar_loc,     ph0); ph0 ^= 1; }
            else          { mbar_wait(mbar_loc + 8, ph1); ph1 ^= 1; }
        }
        if (warp == 0 && lane < RPC) sym_sh[lane] = symr;

        // -- rinv for b = lane&7: max over 8 source ranks' lmax --
        const uint32_t* pbuf = p_w + buf * (CPC * BLKW);
        float mx;
        {
            int q = lane >> 3;
            float ma = __uint_as_float(pbuf[q * BLKW + 256 + eb]);
            float mb2 = __uint_as_float(pbuf[(q + 4) * BLKW + 256 + eb]);
            mx = fmaxf(ma, mb2);
            mx = fmaxf(mx, __shfl_xor_sync(0xFFFFFFFFu, mx, 8));
            mx = fmaxf(mx, __shfl_xor_sync(0xFFFFFFFFu, mx, 16));
        }
        const float rv = 1.0f / mx;
        if (warp == 0 && lane < RPC) c_sh[lane] += (double)logf(mx);

        // -- B fragments: word kwp = kh*128 + kc*8 + tig -> (rank, sp, b=gid)
        uint32_t bf0[16], bf1[16];
#pragma unroll
        for (int kc = 0; kc < 16; kc++) {
            int w  = kh * 128 + kc * 8 + tig;
            int a0 = (w >> 5) * BLKW + (w & 31) * 8 + gid;
            int a1 = ((w + 4) >> 5) * BLKW + ((w + 4) & 31) * 8 + gid;
            bf0[kc] = pbuf[a0];
            bf1[kc] = pbuf[a1];
        }

        // -- 16 HMMA over 8 interleaved accumulator chains --
        float acc[8][4];
#pragma unroll
        for (int j = 0; j < 8; j++) { acc[j][0] = acc[j][1] = acc[j][2] = acc[j][3] = 0.f; }
#pragma unroll
        for (int kc = 0; kc < 16; kc++)
            mma16816(acc[kc & 7], areg[kc], bf0[kc], bf1[kc]);
#pragma unroll
        for (int cjs = 0; cjs < 4; cjs++) {
            float d = ((acc[0][cjs] + acc[1][cjs]) + (acc[2][cjs] + acc[3][cjs]))
                    + ((acc[4][cjs] + acc[5][cjs]) + (acc[6][cjs] + acc[7][cjs]));
            int row = 2 * tig + (cjs & 1);
            int m   = mt * 16 + gid + (cjs >> 1) * 8;
            part[buf][kh][row][m] = d;
        }
        __syncthreads();                             // sync #1

        // -- epilogue: (b = eb, states 2*esp, 2*esp+1) --
        {
            const int sy = sym_sh[eb];
            float2 q0 = *reinterpret_cast<const float2*>(&part[buf][0][eb][esp * 2]);
            float2 q1 = *reinterpret_cast<const float2*>(&part[buf][1][eb][esp * 2]);
            float2 be = *reinterpret_cast<const float2*>(&B_sh[sy][esp * 2]);
            float u0 = (q0.x + q1.x) * rv * be.x;
            float u1 = (q0.y + q1.y) * rv * be.y;
            stg[bufn * BLKW + esp * 8 + eb] = bf16x2(u1, u0);
            float wm = fmaxf(u0, u1);
            wm = fmaxf(wm, __shfl_xor_sync(0xFFFFFFFFu, wm, 8));
            wm = fmaxf(wm, __shfl_xor_sync(0xFFFFFFFFu, wm, 16));
            if (lane < 8) wmax[warp][lane] = wm;     // per-warp max for b=lane
        }
        __syncthreads();                             // sync #2

        // -- warp 0: fold warp maxes, stage lmax, fence, 8 bulk pushes --
        if (warp == 0) {
            int w8 = lane >> 3;
            float m = fmaxf(wmax[w8][eb], wmax[w8 + 4][eb]);
            m = fmaxf(m, __shfl_xor_sync(0xFFFFFFFFu, m, 8));
            m = fmaxf(m, __shfl_xor_sync(0xFFFFFFFFu, m, 16));
            if (lane < 8) stg[bufn * BLKW + 256 + lane] = __float_as_uint(m);
            __syncwarp();
            if (lane < CPC) {
                asm volatile("fence.proxy.async;" ::: "memory");
                blkcp_s2s(p_rem[lane] + (uint32_t)(bufn * CPC + r) * BLKB,
                          stg_base + (uint32_t)bufn * BLKB,
                          BLKB, mbar_rem[lane] + (uint32_t)(bufn << 3));
            }
        }
        buf = bufn;
    }

    // final wait: last step's data
    if (buf == 0) { mbar_wait(mbar_loc,     ph0); }
    else          { mbar_wait(mbar_loc + 8, ph1); }

    // ---- alpha_T = log(u_T) + C (own slice: rank r's block) ----
    {
        uint32_t pw = p_w[buf * (CPC * BLKW) + r * BLKW + esp * 8 + eb];
        float u0 = __uint_as_float(pw << 16);
        float u1 = __uint_as_float(pw & 0xFFFF0000u);
        double cc = c_sh[eb];
        int s0 = col0 + esp * 2;
        out[(size_t)(cl * RPC + eb) * NS + s0]     = (float)((double)logf(u0) + cc);
        out[(size_t)(cl * RPC + eb) * NS + s0 + 1] = (float)((double)logf(u1) + cc);
    }
    asm volatile("barrier.cluster.arrive.aligned;" ::: "memory");
    asm volatile("barrier.cluster.wait.aligned;"   ::: "memory");
}

// ---------------------------------------------------------------------------
// Kernel 2: loglik[b] = log(sum_s exp(alpha - m) + S*eps) + m, one warp per row
// ---------------------------------------------------------------------------
__global__ void loglik_kernel(float* __restrict__ out) {
    const int b    = blockIdx.x;
    const int lane = threadIdx.x;
    const float* a = out + (size_t)b * NS;
    float v[16];
    float m = -3.0e38f;
#pragma unroll
    for (int i = 0; i < 16; i++) { v[i] = a[lane + i * 32]; m = fmaxf(m, v[i]); }
#pragma unroll
    for (int o = 16; o >= 1; o >>= 1) m = fmaxf(m, __shfl_xor_sync(0xFFFFFFFFu, m, o));
    float s = 0.f;
#pragma unroll
    for (int i = 0; i < 16; i++) s += expf(v[i] - m);
#pragma unroll
    for (int o = 16; o >= 1; o >>= 1) s += __shfl_xor_sync(0xFFFFFFFFu, s, o);
    if (lane == 0) out[NB * NS + b] = logf(s + 512.0f * 1e-16f) + m;
}

// ---------------------------------------------------------------------------
extern "C" void kernel_launch(void* const* d_in, const int* in_sizes, int n_in,
                              void* d_out, int out_size) {
    const float* x  = nullptr;
    const float* A  = nullptr;
    const float* Bm = nullptr;
    for (int i = 0; i < n_in; i++) {
        if      (in_sizes[i] == NB * TB * NM) x  = (const float*)d_in[i];
        else if (in_sizes[i] == NS * NS)      A  = (const float*)d_in[i];
        else if (in_sizes[i] == NM * NS)      Bm = (const float*)d_in[i];
    }
    if (!x  && n_in > 0) x  = (const float*)d_in[0];
    if (!A  && n_in > 1) A  = (const float*)d_in[1];
    if (!Bm && n_in > 2) Bm = (const float*)d_in[2];

    float* out = (float*)d_out;

    cudaFuncSetAttribute(hmm_fwd_kernel,
                         cudaFuncAttributeMaxDynamicSharedMemorySize, SM_TOTAL);

    extract_sym_kernel<<<(NB * TB * 4) / 256, 256>>>(x);
    hmm_fwd_kernel<<<NCL * CPC, 256, SM_TOTAL>>>(A, Bm, out);
    if (out_size >= NB * NS + NB)
        loglik_kernel<<<NB, 32>>>(out);
}

// round 13
// speedup vs baseline: 1.4684x; 1.4684x over previous
#include <cuda_runtime.h>
#include <math.h>
#include <stdint.h>

// Problem constants
#define TB   8192   // T
#define NB   128    // batch
#define NS   512    // states
#define NM   64     // symbols
#define NCL  16     // clusters (batch groups)
#define RPC  8      // batch rows per cluster
#define CPC  8      // CTAs per cluster (state slices)
#define NC   64     // state columns per CTA
#define RSW  260    // p row stride in 32-bit words (256 data + 4 pad)
#define PSD  76     // part s-dim pad (conflict-free ST + LD)
#define TXH  4224   // expected tx bytes per half: 4 src * (1024 p + 32 lmax)

// Static device scratch
__device__ unsigned short g_sym[NB * TB];            // 2 MB: symbol per (b,t)

// ---- helpers ---------------------------------------------------------------
__device__ __forceinline__ uint32_t bf16x2(float hi, float lo) {
    uint32_t d;
    asm("cvt.rn.bf16x2.f32 %0, %1, %2;" : "=r"(d) : "f"(hi), "f"(lo));
    return d;
}
__device__ __forceinline__ void mma16816(float* d, const uint32_t* a,
                                         uint32_t b0, uint32_t b1) {
    asm("mma.sync.aligned.m16n8k16.row.col.f32.bf16.bf16.f32 "
        "{%0,%1,%2,%3}, {%4,%5,%6,%7}, {%8,%9}, {%0,%1,%2,%3};"
        : "+f"(d[0]), "+f"(d[1]), "+f"(d[2]), "+f"(d[3])
        : "r"(a[0]), "r"(a[1]), "r"(a[2]), "r"(a[3]), "r"(b0), "r"(b1));
}
__device__ __forceinline__ uint32_t mapa_sh(uint32_t addr, uint32_t rank) {
    uint32_t d;
    asm("mapa.shared::cluster.u32 %0, %1, %2;" : "=r"(d) : "r"(addr), "r"(rank));
    return d;
}
__device__ __forceinline__ uint32_t smem_u32(const void* p) {
    uint32_t a;
    asm("{ .reg .u64 t; cvta.to.shared.u64 t, %1; cvt.u32.u64 %0, t; }"
        : "=r"(a) : "l"(p));
    return a;
}
__device__ __forceinline__ void st_async64(uint32_t raddr, unsigned long long v,
                                           uint32_t rmbar) {
    asm volatile("st.async.shared::cluster.mbarrier::complete_tx::bytes.u64 "
                 "[%0], %1, [%2];" :: "r"(raddr), "l"(v), "r"(rmbar) : "memory");
}
__device__ __forceinline__ void st_async32(uint32_t raddr, uint32_t v,
                                           uint32_t rmbar) {
    asm volatile("st.async.shared::cluster.mbarrier::complete_tx::bytes.u32 "
                 "[%0], %1, [%2];" :: "r"(raddr), "r"(v), "r"(rmbar) : "memory");
}
__device__ __forceinline__ void mbar_init(uint32_t addr, uint32_t count) {
    asm volatile("mbarrier.init.shared.b64 [%0], %1;" :: "r"(addr), "r"(count)
                 : "memory");
}
__device__ __forceinline__ void mbar_arm(uint32_t addr, uint32_t tx) {
    asm volatile("mbarrier.arrive.expect_tx.shared.b64 _, [%0], %1;"
                 :: "r"(addr), "r"(tx) : "memory");
}
__device__ __forceinline__ void mbar_wait(uint32_t addr, int parity) {
    asm volatile(
        "{\n\t.reg .pred P;\n"
        "W%=:\n\t"
        "mbarrier.try_wait.parity.acquire.cluster.shared::cta.b64 P, [%0], %1, 0x989680;\n\t"
        "@P bra D%=;\n\t"
        "bra W%=;\n"
        "D%=:\n\t}"
        :: "r"(addr), "r"(parity) : "memory");
}

// ---------------------------------------------------------------------------
// Kernel 0: collapse one-hot x[b,t,:] -> symbol index. 4 threads per position.
// ---------------------------------------------------------------------------
__global__ void extract_sym_kernel(const float* __restrict__ x) {
    int g = blockIdx.x * blockDim.x + threadIdx.x;
    int pos  = g >> 2;
    int part = g & 3;
    const float4* xp = reinterpret_cast<const float4*>(x) + (size_t)pos * 16 + part * 4;
    int found = 0;
#pragma unroll
    for (int i = 0; i < 4; i++) {
        float4 v = xp[i];
        int base = part * 16 + i * 4;
        if (v.x > 0.5f) found = base;
        if (v.y > 0.5f) found = base + 1;
        if (v.z > 0.5f) found = base + 2;
        if (v.w > 0.5f) found = base + 3;
    }
    found = max(found, __shfl_xor_sync(0xFFFFFFFFu, found, 1));
    found = max(found, __shfl_xor_sync(0xFFFFFFFFu, found, 2));
    if (part == 0) g_sym[pos] = (unsigned short)found;
}

// ---------------------------------------------------------------------------
// Kernel 1: persistent clustered forward recurrence, bf16 HMMA + fp32 accum,
//   st.async data-driven sync with PER-K-HALF mbarriers (no cluster barrier).
//   grid = 128 CTAs, cluster (8,1,1), 256 threads.
//   MMA phase:  warp w -> (mt = w&3 m16-tile, kh = w>>2 K-half), 16 HMMA.
//               kh warps wait ONLY on their half's barrier (ranks 4kh..4kh+3).
//   Epilogue:   warp w -> batch row b=w; even lanes push ranks 0-3, odd 4-7.
// ---------------------------------------------------------------------------
__global__ void __cluster_dims__(CPC, 1, 1) __launch_bounds__(256, 1)
hmm_fwd_kernel(const float* __restrict__ A, const float* __restrict__ Bm,
               float* __restrict__ out)
{
    __shared__ uint32_t p_w[2][RPC][RSW];          // bf16-pair p, double buffered
    __shared__ float    part[2][2][RPC][PSD];      // [buf][kh][n][m] partials
    __shared__ float    B_sh[NM][NC];              // emission slice
    __shared__ float    lmax[2][RPC][8];           // per-CTA slice maxes [buf][b][r]
    __shared__ float    halfmax[2][RPC];           // per-half folded maxes [kh][b]
    __shared__ double   c_sh[RPC];                 // running log-scale per row
    __shared__ __align__(8) unsigned long long mbar_sh[4];   // [buf][half]

    const int tid  = threadIdx.x;
    const int lane = tid & 31;
    const int warp = tid >> 5;
    const int gid  = lane >> 2;   // mma group id
    const int tig  = lane & 3;    // thread in group
    const int mt   = warp & 3;    // m16 tile
    const int kh   = warp >> 2;   // K-half

    uint32_t r_;
    asm("mov.u32 %0, %%cluster_ctarank;" : "=r"(r_));
    const int r    = (int)r_;
    const int cl   = (int)blockIdx.x / CPC;
    const int col0 = r * NC;
    const uint32_t myhalf8 = (uint32_t)((r >> 2) << 3);  // our slice's half *8

    const uint32_t p_base    = smem_u32(&p_w[0][0][0]);
    const uint32_t lmax_base = smem_u32(&lmax[0][0][0]);
    const uint32_t mbar_loc  = smem_u32(&mbar_sh[0]);
    uint32_t p_rem[CPC], lmax_rem[CPC], mbar_rem[CPC];
#pragma unroll
    for (int rr = 0; rr < CPC; rr++) {
        p_rem[rr]    = mapa_sh(p_base, rr);
        lmax_rem[rr] = mapa_sh(lmax_base, rr);
        mbar_rem[rr] = mapa_sh(mbar_loc, rr);
    }

    if (tid == 0) {
        mbar_init(mbar_loc,      1); mbar_init(mbar_loc + 8,  1);
        mbar_init(mbar_loc + 16, 1); mbar_init(mbar_loc + 24, 1);
    }

    // ---- A fragments (constant): areg[16 kc][4], this warp's (mt, kh) ----
    uint32_t areg[16][4];
#pragma unroll
    for (int kc = 0; kc < 16; kc++) {
        int m0 = col0 + mt * 16 + gid;
        int k0 = kh * 256 + kc * 16 + tig * 2;
        const float* A0 = A + (size_t)k0 * NS;
        areg[kc][0] = bf16x2(A0[NS + m0],          A0[m0]);
        areg[kc][1] = bf16x2(A0[NS + m0 + 8],      A0[m0 + 8]);
        areg[kc][2] = bf16x2(A0[9 * NS + m0],      A0[8 * NS + m0]);
        areg[kc][3] = bf16x2(A0[9 * NS + m0 + 8],  A0[8 * NS + m0 + 8]);
    }

    // ---- emission slice (fp32) ----
    for (int i = tid; i < NM * NC; i += 256)
        B_sh[i >> 6][i & 63] = Bm[(size_t)(i >> 6) * NS + col0 + (i & 63)];

    if (tid < RPC) c_sh[tid] = 0.0;

    // ---- init buffer 0: p[b][k] = (k==0) ? B[sym0][0] : 0 (bf16 pairs) ----
    for (int i = tid; i < RPC * RSW; i += 256) {
        int b = i / RSW, w = i % RSW;
        uint32_t v = 0;
        if (w == 0) {
            int s0 = g_sym[(size_t)(cl * RPC + b) * TB];
            v = bf16x2(0.0f, Bm[(size_t)s0 * NS]);
        }
        p_w[0][b][w] = v;
    }
    if (tid < RPC * 8) {
        int b = tid >> 3;
        int s0 = g_sym[(size_t)(cl * RPC + b) * TB];
        lmax[0][b][tid & 7] = Bm[(size_t)s0 * NS];
    }
    __syncthreads();
    asm volatile("barrier.cluster.arrive.aligned;" ::: "memory");
    asm volatile("barrier.cluster.wait.aligned;"   ::: "memory");

    int buf = 0, ph0 = 0, ph1 = 0;   // parities for this warp's half barrier
    for (int t = 1; t < TB; t++) {
        const int bufn = buf ^ 1;
        // symbol for this warp's epilogue row (independent; overlaps wait)
        const unsigned short symw = __ldg(&g_sym[(size_t)(cl * RPC + warp) * TB + t]);

        // arm both half-barriers of the incoming buffer
        if (tid == 0) {
            mbar_arm(mbar_loc + (bufn << 4),     TXH);
            mbar_arm(mbar_loc + (bufn << 4) + 8, TXH);
        }

        // wait ONLY for this warp's K-half of last step's data
        if (t > 1) {
            uint32_t ba = mbar_loc + (buf << 4) + (kh << 3);
            if (buf == 0) { mbar_wait(ba, ph0); ph0 ^= 1; }
            else          { mbar_wait(ba, ph1); ph1 ^= 1; }
        }

        // -- B fragments for (b = gid, K-half kh): ranks 4kh..4kh+3 only --
        const uint32_t* pb = &p_w[buf][0][0];
        uint32_t bf0[16], bf1[16];
#pragma unroll
        for (int kc = 0; kc < 16; kc++) {
            int w0 = gid * RSW + kh * 128 + kc * 8 + tig;
            bf0[kc] = pb[w0];
            bf1[kc] = pb[w0 + 4];
        }

        // -- 16 HMMA over 8 interleaved accumulator chains --
        float acc[8][4];
#pragma unroll
        for (int j = 0; j < 8; j++) { acc[j][0] = acc[j][1] = acc[j][2] = acc[j][3] = 0.f; }
#pragma unroll
        for (int kc = 0; kc < 16; kc++)
            mma16816(acc[kc & 7], areg[kc], bf0[kc], bf1[kc]);
#pragma unroll
        for (int cjs = 0; cjs < 4; cjs++) {
            float d = ((acc[0][cjs] + acc[1][cjs]) + (acc[2][cjs] + acc[3][cjs]))
                    + ((acc[4][cjs] + acc[5][cjs]) + (acc[6][cjs] + acc[7][cjs]));
            int row = 2 * tig + (cjs & 1);
            int m   = mt * 16 + gid + (cjs >> 1) * 8;
            part[buf][kh][row][m] = d;
        }

        // -- pre-sync: fold THIS half's lmax (ranks 4kh..4kh+3), warps 0 & 4 --
        {
            float v = lmax[buf][lane & 7][4 * kh + (lane >> 3)];
            v = fmaxf(v, __shfl_xor_sync(0xFFFFFFFFu, v, 8));
            v = fmaxf(v, __shfl_xor_sync(0xFFFFFFFFu, v, 16));
            if ((warp == 0 || warp == 4) && lane < 8)
                halfmax[kh][lane] = v;
        }
        __syncthreads();

        // -- epilogue: warp = batch row b=warp, lane = state pair --
        const int s0 = lane * 2;
        const float mx = fmaxf(halfmax[0][warp], halfmax[1][warp]);
        const float rv = 1.0f / mx;
        if (warp == 0 && lane < RPC)
            c_sh[lane] += (double)logf(fmaxf(halfmax[0][lane], halfmax[1][lane]));
        float2 q0 = *reinterpret_cast<const float2*>(&part[buf][0][warp][s0]);
        float2 q1 = *reinterpret_cast<const float2*>(&part[buf][1][warp][s0]);
        float2 be = *reinterpret_cast<const float2*>(&B_sh[symw][s0]);
        float u0 = (q0.x + q1.x) * rv * be.x;
        float u1 = (q0.y + q1.y) * rv * be.y;
        uint32_t pw    = bf16x2(u1, u0);
        uint32_t other = __shfl_xor_sync(0xFFFFFFFFu, pw, 1);
        uint32_t lo = (lane & 1) ? other : pw;
        uint32_t hi = (lane & 1) ? pw : other;
        unsigned long long v2 = ((unsigned long long)hi << 32) | lo;
        uint32_t off = (uint32_t)((bufn * RPC + warp) * RSW + (col0 >> 1) + (lane & ~1)) * 4u;
        const uint32_t rmb_off = (uint32_t)(bufn << 4) + myhalf8;
        const int rb = (lane & 1) * 4;    // even lanes -> ranks 0-3, odd -> 4-7
#pragma unroll
        for (int j = 0; j < 4; j++)
            st_async64(p_rem[rb + j] + off, v2, mbar_rem[rb + j] + rmb_off);

        // per-(CTA, b) slice max -> all ranks' lmax[bufn][warp][r]
        float wm = fmaxf(u0, u1);
#pragma unroll
        for (int o = 16; o >= 1; o >>= 1)
            wm = fmaxf(wm, __shfl_xor_sync(0xFFFFFFFFu, wm, o));
        if (lane < CPC) {
            uint32_t lo2 = (uint32_t)((bufn * RPC + warp) * 8 + r) * 4u;
            st_async32(lmax_rem[lane] + lo2, __float_as_uint(wm),
                       mbar_rem[lane] + rmb_off);
        }
        buf = bufn;
    }

    // final wait: this warp's half of the last step's data, then join
    {
        uint32_t ba = mbar_loc + (buf << 4) + (kh << 3);
        if (buf == 0) { mbar_wait(ba, ph0); }
        else          { mbar_wait(ba, ph1); }
    }
    __syncthreads();

    // ---- alpha_T = log(u_T) + C ----
    {
        const int b  = warp;
        const int s0 = lane * 2;
        uint32_t pw = p_w[buf][b][(col0 >> 1) + lane];
        float u0 = __uint_as_float(pw << 16);
        float u1 = __uint_as_float(pw & 0xFFFF0000u);
        double cc = c_sh[b];
        out[(size_t)(cl * RPC + b) * NS + col0 + s0]     = (float)((double)logf(u0) + cc);
        out[(size_t)(cl * RPC + b) * NS + col0 + s0 + 1] = (float)((double)logf(u1) + cc);
    }
    asm volatile("barrier.cluster.arrive.aligned;" ::: "memory");
    asm volatile("barrier.cluster.wait.aligned;"   ::: "memory");
}

// ---------------------------------------------------------------------------
// Kernel 2: loglik[b] = log(sum_s exp(alpha - m) + S*eps) + m, one warp per row
// ---------------------------------------------------------------------------
__global__ void loglik_kernel(float* __restrict__ out) {
    const int b    = blockIdx.x;
    const int lane = threadIdx.x;
    const float* a = out + (size_t)b * NS;
    float v[16];
    float m = -3.0e38f;
#pragma unroll
    for (int i = 0; i < 16; i++) { v[i] = a[lane + i * 32]; m = fmaxf(m, v[i]); }
#pragma unroll
    for (int o = 16; o >= 1; o >>= 1) m = fmaxf(m, __shfl_xor_sync(0xFFFFFFFFu, m, o));
    float s = 0.f;
#pragma unroll
    for (int i = 0; i < 16; i++) s += expf(v[i] - m);
#pragma unroll
    for (int o = 16; o >= 1; o >>= 1) s += __shfl_xor_sync(0xFFFFFFFFu, s, o);
    if (lane == 0) out[NB * NS + b] = logf(s + 512.0f * 1e-16f) + m;
}

// ---------------------------------------------------------------------------
extern "C" void kernel_launch(void* const* d_in, const int* in_sizes, int n_in,
                              void* d_out, int out_size) {
    const float* x  = nullptr;
    const float* A  = nullptr;
    const float* Bm = nullptr;
    for (int i = 0; i < n_in; i++) {
        if      (in_sizes[i] == NB * TB * NM) x  = (const float*)d_in[i];
        else if (in_sizes[i] == NS * NS)      A  = (const float*)d_in[i];
        else if (in_sizes[i] == NM * NS)      Bm = (const float*)d_in[i];
    }
    if (!x  && n_in > 0) x  = (const float*)d_in[0];
    if (!A  && n_in > 1) A  = (const float*)d_in[1];
    if (!Bm && n_in > 2) Bm = (const float*)d_in[2];

    float* out = (float*)d_out;

    extract_sym_kernel<<<(NB * TB * 4) / 256, 256>>>(x);
    hmm_fwd_kernel<<<NCL * CPC, 256>>>(A, Bm, out);
    if (out_size >= NB * NS + NB)
        loglik_kernel<<<NB, 32>>>(out);
}